// round 4
// baseline (speedup 1.0000x reference)
#include <cuda_runtime.h>
#include <mma.h>
#include <cstdint>
#include <cstddef>

using namespace nvcuda;

#define B_ 32
#define L_ 512
#define D_ 768
#define H_ 12

// ---------------- scratch (static device arrays; no allocation) ----------------
__device__ float g_qh[(size_t)B_*L_*D_];
__device__ float g_kh[(size_t)B_*L_*D_];
__device__ float g_vh[(size_t)B_*L_*D_];
__device__ float g_qt[(size_t)B_*L_*D_];
__device__ float g_ctx[(size_t)B_*L_*D_];
__device__ float g_x[(size_t)B_*L_*D_];
__device__ float g_sw[(size_t)B_*L_*72];
__device__ int   g_mask_mode;

// ---------------- mask dtype detection ----------------
__global__ void detect_mask_k(const unsigned int* __restrict__ w) {
    __shared__ int sF, sO;
    if (threadIdx.x == 0) { sF = 0; sO = 0; }
    __syncthreads();
    int f = 0, o = 0;
    for (int i = threadIdx.x; i < 4096; i += 256) {
        unsigned v = w[i];
        if (v == 0x3F800000u) f = 1;
        else if (v > 1u) o = 1;
    }
    if (f) atomicOr(&sF, 1);
    if (o) atomicOr(&sO, 1);
    __syncthreads();
    if (threadIdx.x == 0) g_mask_mode = sF ? 1 : (sO ? 2 : 0);
}

__device__ __forceinline__ int is_masked(const void* mp, int idx, int mode) {
    if (mode == 2) return ((const unsigned char*)mp)[idx] != 0;
    if (mode == 1) return ((const float*)mp)[idx] != 0.0f;
    return ((const int*)mp)[idx] != 0;
}

// ---------------- qt = q + txt broadcast ----------------
__global__ void add_txt_k(const float* __restrict__ q, const float* __restrict__ txt) {
    size_t idx = (size_t)blockIdx.x * 256 + threadIdx.x;
    if (idx >= (size_t)B_*L_*D_) return;
    int b = (int)(idx / ((size_t)L_*D_));
    int c = (int)(idx % D_);
    g_qt[idx] = q[idx] + txt[b*D_ + c];
}

// ---------------- generic batched tf32 GEMM ----------------
// C = alpha * A @ B (+bias)(+resid); TRANSB: B stored [N,K] row-major (i.e. A@B^T)
template<bool TRANSB>
__global__ __launch_bounds__(256) void gemm_k(
    const float* __restrict__ A, const float* __restrict__ Bm, float* __restrict__ C,
    const float* __restrict__ bias, const float* __restrict__ resid,
    int M, int N, int K, int lda, int ldb, int ldc,
    long long aSB, long long aSH, long long bSB, long long bSH,
    long long cSB, long long cSH, int Hp, float alpha)
{
    __shared__ float As[128*16];
    __shared__ float Bs[16*72];
    __shared__ float Cs[128*68];
    int zb = blockIdx.z / Hp, zh = blockIdx.z % Hp;
    const float* Ab = A + zb*aSB + zh*aSH;
    const float* Bb = Bm + zb*bSB + zh*bSH;
    float* Cb = C + zb*cSB + zh*cSH;
    int m0 = blockIdx.x*128, n0 = blockIdx.y*64;
    int tid = threadIdx.x, wid = tid>>5;
    int wm = wid>>1, wn = wid&1;

    wmma::fragment<wmma::accumulator,16,16,8,float> acc[2][2];
    #pragma unroll
    for (int i=0;i<2;i++)
    #pragma unroll
    for (int j=0;j<2;j++) wmma::fill_fragment(acc[i][j], 0.f);

    for (int kt=0; kt<K; kt+=16) {
        __syncthreads();
        #pragma unroll
        for (int i=0;i<2;i++) {
            int f = tid*2+i; int r=f>>2, c=f&3;
            *(float4*)(As + r*16 + c*4) =
                *(const float4*)(Ab + (size_t)(m0+r)*lda + kt + c*4);
        }
        if (TRANSB) {
            int n = tid>>2, c = tid&3;
            *(float4*)(Bs + n*16 + c*4) =
                *(const float4*)(Bb + (size_t)(n0+n)*ldb + kt + c*4);
        } else {
            int r = tid>>4, c = (tid&15)*4;
            const float* bp = Bb + (size_t)(kt+r)*ldb + n0;
            float4 v;
            v.x = (n0+c+0<N)? bp[c+0]:0.f;
            v.y = (n0+c+1<N)? bp[c+1]:0.f;
            v.z = (n0+c+2<N)? bp[c+2]:0.f;
            v.w = (n0+c+3<N)? bp[c+3]:0.f;
            *(float4*)(Bs + r*72 + c) = v;
        }
        __syncthreads();
        #pragma unroll
        for (int kk=0; kk<16; kk+=8) {
            wmma::fragment<wmma::matrix_a,16,16,8,wmma::precision::tf32,wmma::row_major> af[2];
            #pragma unroll
            for (int i=0;i<2;i++) {
                wmma::load_matrix_sync(af[i], As + (wm*32+16*i)*16 + kk, 16);
                #pragma unroll
                for (int t=0;t<af[i].num_elements;t++)
                    af[i].x[t] = wmma::__float_to_tf32(af[i].x[t]);
            }
            if (TRANSB) {
                wmma::fragment<wmma::matrix_b,16,16,8,wmma::precision::tf32,wmma::col_major> bf[2];
                #pragma unroll
                for (int j=0;j<2;j++) {
                    wmma::load_matrix_sync(bf[j], Bs + (wn*32+16*j)*16 + kk, 16);
                    #pragma unroll
                    for (int t=0;t<bf[j].num_elements;t++)
                        bf[j].x[t] = wmma::__float_to_tf32(bf[j].x[t]);
                }
                #pragma unroll
                for (int i=0;i<2;i++)
                #pragma unroll
                for (int j=0;j<2;j++) wmma::mma_sync(acc[i][j], af[i], bf[j], acc[i][j]);
            } else {
                wmma::fragment<wmma::matrix_b,16,16,8,wmma::precision::tf32,wmma::row_major> bf[2];
                #pragma unroll
                for (int j=0;j<2;j++) {
                    wmma::load_matrix_sync(bf[j], Bs + kk*72 + wn*32+16*j, 72);
                    #pragma unroll
                    for (int t=0;t<bf[j].num_elements;t++)
                        bf[j].x[t] = wmma::__float_to_tf32(bf[j].x[t]);
                }
                #pragma unroll
                for (int i=0;i<2;i++)
                #pragma unroll
                for (int j=0;j<2;j++) wmma::mma_sync(acc[i][j], af[i], bf[j], acc[i][j]);
            }
        }
    }
    __syncthreads();
    #pragma unroll
    for (int i=0;i<2;i++)
    #pragma unroll
    for (int j=0;j<2;j++) {
        #pragma unroll
        for (int t=0;t<acc[i][j].num_elements;t++) acc[i][j].x[t] *= alpha;
        wmma::store_matrix_sync(Cs + (wm*32+16*i)*68 + wn*32+16*j, acc[i][j], 68,
                                wmma::mem_row_major);
    }
    __syncthreads();
    #pragma unroll 4
    for (int p=0;p<32;p++) {
        int e = p*256 + tid; int r = e>>6, c = e&63;
        if (n0+c < N) {
            float v = Cs[r*68+c];
            if (bias)  v += bias[n0+c];
            if (resid) v += resid[(size_t)(m0+r)*ldc + n0+c];
            Cb[(size_t)(m0+r)*ldc + n0+c] = v;
        }
    }
}

// ---------------- fused spatial-gate + softmax (in-place on P) ----------------
__global__ __launch_bounds__(256) void fuse_softmax_k(
    const float* __restrict__ ploc, const void* __restrict__ maskp,
    float* __restrict__ P)
{
    int bl = blockIdx.x; int b = bl >> 9;
    __shared__ float splc[512*5];
    __shared__ float ssw[72];
    __shared__ unsigned char smask[512];
    __shared__ float red[8];
    int tid = threadIdx.x;
    const float* pl = ploc + (size_t)bl*512*5;
    for (int i=tid; i<2560; i+=256) splc[i] = pl[i];
    if (tid < 72) ssw[tid] = g_sw[(size_t)bl*72 + tid];
    int mode = g_mask_mode;
    for (int i=tid; i<512; i+=256)
        smask[i] = (unsigned char)is_masked(maskp, b*L_ + i, mode);
    __syncthreads();
    int l = bl & 511;
    for (int h=0; h<H_; h++) {
        float* Srow = P + (((size_t)b*H_ + h)*L_ + l)*L_;
        float b0 = ssw[h*6], w0=ssw[h*6+1], w1=ssw[h*6+2], w2=ssw[h*6+3],
              w3=ssw[h*6+4], w4=ssw[h*6+5];
        float x0, x1;
        {
            int t = tid;
            if (smask[t]) x0 = -INFINITY;
            else {
                const float* pp = splc + t*5;
                float loc = b0 + w0*pp[0]+w1*pp[1]+w2*pp[2]+w3*pp[3]+w4*pp[4];
                float sg = 1.f/(1.f+__expf(-loc));
                x0 = Srow[t] + __logf(fmaxf(sg, 1e-6f));
            }
            t = tid + 256;
            if (smask[t]) x1 = -INFINITY;
            else {
                const float* pp = splc + t*5;
                float loc = b0 + w0*pp[0]+w1*pp[1]+w2*pp[2]+w3*pp[3]+w4*pp[4];
                float sg = 1.f/(1.f+__expf(-loc));
                x1 = Srow[t] + __logf(fmaxf(sg, 1e-6f));
            }
        }
        float mx = fmaxf(x0, x1);
        #pragma unroll
        for (int o=16;o;o>>=1) mx = fmaxf(mx, __shfl_xor_sync(~0u, mx, o));
        if ((tid&31)==0) red[tid>>5] = mx;
        __syncthreads();
        mx = fmaxf(fmaxf(fmaxf(red[0],red[1]),fmaxf(red[2],red[3])),
                   fmaxf(fmaxf(red[4],red[5]),fmaxf(red[6],red[7])));
        float e0 = smask[tid]      ? 0.f : __expf(x0 - mx);
        float e1 = smask[tid+256]  ? 0.f : __expf(x1 - mx);
        float s = e0 + e1;
        #pragma unroll
        for (int o=16;o;o>>=1) s += __shfl_xor_sync(~0u, s, o);
        __syncthreads();
        if ((tid&31)==0) red[tid>>5] = s;
        __syncthreads();
        s = red[0]+red[1]+red[2]+red[3]+red[4]+red[5]+red[6]+red[7];
        float inv = 1.f/s;
        Srow[tid] = e0*inv;
        Srow[tid+256] = e1*inv;
        __syncthreads();
    }
}

// ---------------- LayerNorm ----------------
__global__ __launch_bounds__(256) void ln_k(
    const float* __restrict__ sc, const float* __restrict__ bs, float* __restrict__ Y)
{
    int row = blockIdx.x;
    const float* x = g_x + (size_t)row*D_;
    float* y = Y + (size_t)row*D_;
    __shared__ float r1[8], r2[8];
    int tid = threadIdx.x;
    float v0=x[tid], v1=x[tid+256], v2=x[tid+512];
    float s = v0+v1+v2, q = v0*v0+v1*v1+v2*v2;
    #pragma unroll
    for (int o=16;o;o>>=1) {
        s += __shfl_xor_sync(~0u, s, o);
        q += __shfl_xor_sync(~0u, q, o);
    }
    if ((tid&31)==0) { r1[tid>>5]=s; r2[tid>>5]=q; }
    __syncthreads();
    s = r1[0]+r1[1]+r1[2]+r1[3]+r1[4]+r1[5]+r1[6]+r1[7];
    q = r2[0]+r2[1]+r2[2]+r2[3]+r2[4]+r2[5]+r2[6]+r2[7];
    float mu = s * (1.f/D_);
    float var = q * (1.f/D_) - mu*mu;
    float r = rsqrtf(var + 1e-5f);
    y[tid]     = (v0-mu)*r*sc[tid]     + bs[tid];
    y[tid+256] = (v1-mu)*r*sc[tid+256] + bs[tid+256];
    y[tid+512] = (v2-mu)*r*sc[tid+512] + bs[tid+512];
}

// ---------------- host ----------------
extern "C" void kernel_launch(void* const* d_in, const int* in_sizes, int n_in,
                              void* d_out, int out_size) {
    const float* q    = (const float*)d_in[0];
    const float* k    = (const float*)d_in[1];
    const float* v    = (const float*)d_in[2];
    const float* ploc = (const float*)d_in[3];
    const float* txt  = (const float*)d_in[4];
    const void*  mask = d_in[5];
    const float* Wq = (const float*)d_in[6],  *bq = (const float*)d_in[7];
    const float* Wk = (const float*)d_in[8],  *bk = (const float*)d_in[9];
    const float* Wv = (const float*)d_in[10], *bv = (const float*)d_in[11];
    const float* Wfc= (const float*)d_in[12], *bfc= (const float*)d_in[13];
    const float* Wc = (const float*)d_in[14], *bc = (const float*)d_in[15];
    const float* lns= (const float*)d_in[16], *lnb= (const float*)d_in[17];

    float* y = (float*)d_out;
    float* P = y + (size_t)B_*L_*D_;          // fused_attn region (B,H,L,L)

    void *qh_, *kh_, *vh_, *qt_, *ctx_, *x_, *sw_;
    cudaGetSymbolAddress(&qh_, g_qh);  cudaGetSymbolAddress(&kh_, g_kh);
    cudaGetSymbolAddress(&vh_, g_vh);  cudaGetSymbolAddress(&qt_, g_qt);
    cudaGetSymbolAddress(&ctx_, g_ctx); cudaGetSymbolAddress(&x_, g_x);
    cudaGetSymbolAddress(&sw_, g_sw);
    float* qh = (float*)qh_; float* kh = (float*)kh_; float* vh = (float*)vh_;
    float* qt = (float*)qt_; float* ctx = (float*)ctx_; float* xx = (float*)x_;
    float* sw = (float*)sw_;

    const int M = B_*L_;
    detect_mask_k<<<1,256>>>((const unsigned int*)mask);
    add_txt_k<<<(M*D_ + 255)/256, 256>>>(q, txt);

    // projections: (B*L,768) @ (768,768)
    gemm_k<false><<<dim3(M/128, 12, 1), 256>>>(q, Wq, qh, bq, nullptr,
        M, D_, D_, D_, D_, D_, 0,0,0,0,0,0, 1, 1.f);
    gemm_k<false><<<dim3(M/128, 12, 1), 256>>>(k, Wk, kh, bk, nullptr,
        M, D_, D_, D_, D_, D_, 0,0,0,0,0,0, 1, 1.f);
    gemm_k<false><<<dim3(M/128, 12, 1), 256>>>(v, Wv, vh, bv, nullptr,
        M, D_, D_, D_, D_, D_, 0,0,0,0,0,0, 1, 1.f);
    // cond: (B*L,768) @ (768,72)
    gemm_k<false><<<dim3(M/128, 2, 1), 256>>>(qt, Wc, sw, bc, nullptr,
        M, 72, D_, D_, 72, 72, 0,0,0,0,0,0, 1, 1.f);
    // S = scale * Q @ K^T  per (b,h), written into P region of d_out
    gemm_k<true><<<dim3(4, 8, B_*H_), 256>>>(qh, kh, P, nullptr, nullptr,
        L_, L_, 64, D_, D_, L_,
        (long long)L_*D_, 64, (long long)L_*D_, 64,
        (long long)H_*L_*L_, (long long)L_*L_, H_, 0.125f);
    // fused spatial gate + masked softmax, in place on P
    fuse_softmax_k<<<M, 256>>>(ploc, mask, P);
    // ctx = P @ V  per (b,h)
    gemm_k<false><<<dim3(4, 1, B_*H_), 256>>>(P, vh, ctx, nullptr, nullptr,
        L_, 64, L_, L_, D_, D_,
        (long long)H_*L_*L_, (long long)L_*L_,
        (long long)L_*D_, 64, (long long)L_*D_, 64, H_, 1.f);
    // x = ctx @ Wfc + bfc + q
    gemm_k<false><<<dim3(M/128, 12, 1), 256>>>(ctx, Wfc, xx, bfc, q,
        M, D_, D_, D_, D_, D_, 0,0,0,0,0,0, 1, 1.f);
    // y = LayerNorm(x)
    ln_k<<<M, 256>>>(lns, lnb, y);
}

// round 5
// speedup vs baseline: 1.1099x; 1.1099x over previous
#include <cuda_runtime.h>
#include <mma.h>
#include <cstdint>
#include <cstddef>

using namespace nvcuda;

#define B_ 32
#define L_ 512
#define D_ 768
#define H_ 12

// ---------------- scratch (static device arrays; no allocation) ----------------
__device__ float g_qh[(size_t)B_*L_*D_];
__device__ float g_kh[(size_t)B_*L_*D_];
__device__ float g_vh[(size_t)B_*L_*D_];
__device__ float g_qt[(size_t)B_*L_*D_];
__device__ float g_ctx[(size_t)B_*L_*D_];
__device__ float g_x[(size_t)B_*L_*D_];
__device__ float g_sw[(size_t)B_*L_*72];
__device__ int   g_mask_mode;

// ---------------- mask dtype detection ----------------
__global__ void detect_mask_k(const unsigned int* __restrict__ w) {
    __shared__ int sF, sO;
    if (threadIdx.x == 0) { sF = 0; sO = 0; }
    __syncthreads();
    int f = 0, o = 0;
    for (int i = threadIdx.x; i < 4096; i += 256) {
        unsigned v = w[i];
        if (v == 0x3F800000u) f = 1;
        else if (v > 1u) o = 1;
    }
    if (f) atomicOr(&sF, 1);
    if (o) atomicOr(&sO, 1);
    __syncthreads();
    if (threadIdx.x == 0) g_mask_mode = sF ? 1 : (sO ? 2 : 0);
}

__device__ __forceinline__ int is_masked(const void* mp, int idx, int mode) {
    if (mode == 2) return ((const unsigned char*)mp)[idx] != 0;
    if (mode == 1) return ((const float*)mp)[idx] != 0.0f;
    return ((const int*)mp)[idx] != 0;
}

// ---------------- qt = q + txt broadcast ----------------
__global__ void add_txt_k(const float* __restrict__ q, const float* __restrict__ txt) {
    size_t idx = (size_t)blockIdx.x * 256 + threadIdx.x;
    if (idx >= (size_t)B_*L_*D_) return;
    int b = (int)(idx / ((size_t)L_*D_));
    int c = (int)(idx % D_);
    g_qt[idx] = q[idx] + txt[b*D_ + c];
}

// ---------------- batched tf32 GEMM, padded smem, big tiles ----------------
struct GArgs {
    const float *A0,*A1,*A2, *B0,*B1,*B2, *bi0,*bi1,*bi2;
    float *C0,*C1,*C2;
    const float* resid;
    int M,N,K,lda,ldb,ldc,nSets,Hp;
    long long aSB,aSH,bSB,bSH,cSB,cSH;
    float alpha;
};

// C = alpha*A@B (+bias)(+resid). TRANSB: B is [N,K] row-major (A@B^T).
// Block tile 128 x (32*NF). 8 warps as 4x2; warp tile 32 x (16*NF). BK=32.
template<bool TRANSB, int NF>
__global__ __launch_bounds__(256) void gemm_k(GArgs g)
{
    constexpr int BN   = 32*NF;
    constexpr int ASTR = 36;
    constexpr int BSTR = TRANSB ? 36 : (BN+4);
    constexpr int ASZ  = 128*ASTR;
    constexpr int BSZ  = TRANSB ? BN*36 : 32*(BN+4);
    __shared__ float sA[ASZ];
    __shared__ float sB[BSZ];
    __shared__ float stag[8][16*20];

    int z = blockIdx.z;
    int set = z % g.nSets; int rest = z / g.nSets;
    int zh = rest % g.Hp;  int zb = rest / g.Hp;
    const float* A  = (set==0? g.A0 : set==1? g.A1 : g.A2) + zb*g.aSB + zh*g.aSH;
    const float* Bm = (set==0? g.B0 : set==1? g.B1 : g.B2) + zb*g.bSB + zh*g.bSH;
    const float* bias = set==0? g.bi0 : set==1? g.bi1 : g.bi2;
    float* C = (set==0? g.C0 : set==1? g.C1 : g.C2) + zb*g.cSB + zh*g.cSH;

    int m0 = blockIdx.x*128, n0 = blockIdx.y*BN;
    int tid = threadIdx.x, lane = tid&31, wid = tid>>5;
    int wm = wid>>1, wn = wid&1;

    wmma::fragment<wmma::accumulator,16,16,8,float> acc[2][NF];
    #pragma unroll
    for (int i=0;i<2;i++)
    #pragma unroll
    for (int j=0;j<NF;j++) wmma::fill_fragment(acc[i][j], 0.f);

    for (int kt=0; kt<g.K; kt+=32) {
        __syncthreads();
        // A tile: 128x32 (1024 float4, 4/thread), tf32-convert at store
        #pragma unroll
        for (int i=0;i<4;i++) {
            int idx = tid + i*256;
            int r = idx>>3, c = (idx&7)*4;
            float4 v = *(const float4*)(A + (size_t)(m0+r)*g.lda + kt + c);
            v.x = wmma::__float_to_tf32(v.x); v.y = wmma::__float_to_tf32(v.y);
            v.z = wmma::__float_to_tf32(v.z); v.w = wmma::__float_to_tf32(v.w);
            *(float4*)(sA + r*ASTR + c) = v;
        }
        if (TRANSB) {
            // BN x 32 from Bm[N][K]
            #pragma unroll
            for (int i=0;i<(BN*8)/256;i++) {
                int idx = tid + i*256;
                int r = idx>>3, c = (idx&7)*4;
                float4 v = *(const float4*)(Bm + (size_t)(n0+r)*g.ldb + kt + c);
                v.x = wmma::__float_to_tf32(v.x); v.y = wmma::__float_to_tf32(v.y);
                v.z = wmma::__float_to_tf32(v.z); v.w = wmma::__float_to_tf32(v.w);
                *(float4*)(sB + r*36 + c) = v;
            }
        } else {
            // 32 x BN from Bm[K][N], N-bounds checked
            #pragma unroll
            for (int i=0;i<(32*BN/4)/256;i++) {
                int idx = tid + i*256;
                int r = idx/(BN/4), c = (idx%(BN/4))*4;
                const float* bp = Bm + (size_t)(kt+r)*g.ldb + n0 + c;
                float4 v;
                if (n0 + c + 4 <= g.N) v = *(const float4*)bp;
                else {
                    v.x = (n0+c+0<g.N)? bp[0]:0.f; v.y = (n0+c+1<g.N)? bp[1]:0.f;
                    v.z = (n0+c+2<g.N)? bp[2]:0.f; v.w = (n0+c+3<g.N)? bp[3]:0.f;
                }
                v.x = wmma::__float_to_tf32(v.x); v.y = wmma::__float_to_tf32(v.y);
                v.z = wmma::__float_to_tf32(v.z); v.w = wmma::__float_to_tf32(v.w);
                *(float4*)(sB + r*BSTR + c) = v;
            }
        }
        __syncthreads();
        #pragma unroll
        for (int kk=0; kk<32; kk+=8) {
            wmma::fragment<wmma::matrix_a,16,16,8,wmma::precision::tf32,wmma::row_major> af[2];
            #pragma unroll
            for (int i=0;i<2;i++)
                wmma::load_matrix_sync(af[i], sA + (wm*32+16*i)*ASTR + kk, ASTR);
            if (TRANSB) {
                wmma::fragment<wmma::matrix_b,16,16,8,wmma::precision::tf32,wmma::col_major> bf[NF];
                #pragma unroll
                for (int j=0;j<NF;j++)
                    wmma::load_matrix_sync(bf[j], sB + (wn*NF*16+16*j)*36 + kk, 36);
                #pragma unroll
                for (int i=0;i<2;i++)
                #pragma unroll
                for (int j=0;j<NF;j++) wmma::mma_sync(acc[i][j], af[i], bf[j], acc[i][j]);
            } else {
                wmma::fragment<wmma::matrix_b,16,16,8,wmma::precision::tf32,wmma::row_major> bf[NF];
                #pragma unroll
                for (int j=0;j<NF;j++)
                    wmma::load_matrix_sync(bf[j], sB + kk*BSTR + wn*NF*16 + 16*j, BSTR);
                #pragma unroll
                for (int i=0;i<2;i++)
                #pragma unroll
                for (int j=0;j<NF;j++) wmma::mma_sync(acc[i][j], af[i], bf[j], acc[i][j]);
            }
        }
    }

    // epilogue: per-warp staging, vectorized store
    #pragma unroll
    for (int i=0;i<2;i++)
    #pragma unroll
    for (int j=0;j<NF;j++) {
        #pragma unroll
        for (int t=0;t<acc[i][j].num_elements;t++) acc[i][j].x[t] *= g.alpha;
        wmma::store_matrix_sync(stag[wid], acc[i][j], 20, wmma::mem_row_major);
        __syncwarp();
        int mb = m0 + wm*32 + i*16;
        int nb = n0 + wn*NF*16 + j*16;
        int r = lane>>1, c0 = (lane&1)*8;
        const float* src = stag[wid] + r*20 + c0;
        float* dst = C + (size_t)(mb+r)*g.ldc + nb + c0;
        if (nb + 16 <= g.N) {
            float4 v0 = *(const float4*)(src);
            float4 v1 = *(const float4*)(src+4);
            if (bias) {
                float4 b0 = *(const float4*)(bias + nb + c0);
                float4 b1 = *(const float4*)(bias + nb + c0 + 4);
                v0.x+=b0.x; v0.y+=b0.y; v0.z+=b0.z; v0.w+=b0.w;
                v1.x+=b1.x; v1.y+=b1.y; v1.z+=b1.z; v1.w+=b1.w;
            }
            if (g.resid) {
                const float* rp = g.resid + (size_t)(mb+r)*g.ldc + nb + c0;
                float4 r0 = *(const float4*)(rp);
                float4 r1 = *(const float4*)(rp+4);
                v0.x+=r0.x; v0.y+=r0.y; v0.z+=r0.z; v0.w+=r0.w;
                v1.x+=r1.x; v1.y+=r1.y; v1.z+=r1.z; v1.w+=r1.w;
            }
            *(float4*)(dst) = v0;
            *(float4*)(dst+4) = v1;
        } else {
            #pragma unroll
            for (int t=0;t<8;t++) {
                int n = nb + c0 + t;
                if (n < g.N) {
                    float v = src[t];
                    if (bias) v += bias[n];
                    if (g.resid) v += g.resid[(size_t)(mb+r)*g.ldc + n];
                    dst[t] = v;
                }
            }
        }
        __syncwarp();
    }
}

// ---------------- fused spatial-gate + softmax (in-place on P) ----------------
__global__ __launch_bounds__(256) void fuse_softmax_k(
    const float* __restrict__ ploc, const void* __restrict__ maskp,
    float* __restrict__ P)
{
    int bl = blockIdx.x; int b = bl >> 9;
    __shared__ float splc[512*5];
    __shared__ float ssw[72];
    __shared__ unsigned char smask[512];
    __shared__ float red[8];
    int tid = threadIdx.x;
    const float* pl = ploc + (size_t)bl*512*5;
    for (int i=tid; i<2560; i+=256) splc[i] = pl[i];
    if (tid < 72) ssw[tid] = g_sw[(size_t)bl*72 + tid];
    int mode = g_mask_mode;
    for (int i=tid; i<512; i+=256)
        smask[i] = (unsigned char)is_masked(maskp, b*L_ + i, mode);
    __syncthreads();
    int l = bl & 511;
    for (int h=0; h<H_; h++) {
        float* Srow = P + (((size_t)b*H_ + h)*L_ + l)*L_;
        float b0 = ssw[h*6], w0=ssw[h*6+1], w1=ssw[h*6+2], w2=ssw[h*6+3],
              w3=ssw[h*6+4], w4=ssw[h*6+5];
        float x0, x1;
        {
            int t = tid;
            if (smask[t]) x0 = -INFINITY;
            else {
                const float* pp = splc + t*5;
                float loc = b0 + w0*pp[0]+w1*pp[1]+w2*pp[2]+w3*pp[3]+w4*pp[4];
                float sg = 1.f/(1.f+__expf(-loc));
                x0 = Srow[t] + __logf(fmaxf(sg, 1e-6f));
            }
            t = tid + 256;
            if (smask[t]) x1 = -INFINITY;
            else {
                const float* pp = splc + t*5;
                float loc = b0 + w0*pp[0]+w1*pp[1]+w2*pp[2]+w3*pp[3]+w4*pp[4];
                float sg = 1.f/(1.f+__expf(-loc));
                x1 = Srow[t] + __logf(fmaxf(sg, 1e-6f));
            }
        }
        float mx = fmaxf(x0, x1);
        #pragma unroll
        for (int o=16;o;o>>=1) mx = fmaxf(mx, __shfl_xor_sync(~0u, mx, o));
        if ((tid&31)==0) red[tid>>5] = mx;
        __syncthreads();
        mx = fmaxf(fmaxf(fmaxf(red[0],red[1]),fmaxf(red[2],red[3])),
                   fmaxf(fmaxf(red[4],red[5]),fmaxf(red[6],red[7])));
        float e0 = smask[tid]      ? 0.f : __expf(x0 - mx);
        float e1 = smask[tid+256]  ? 0.f : __expf(x1 - mx);
        float s = e0 + e1;
        #pragma unroll
        for (int o=16;o;o>>=1) s += __shfl_xor_sync(~0u, s, o);
        __syncthreads();
        if ((tid&31)==0) red[tid>>5] = s;
        __syncthreads();
        s = red[0]+red[1]+red[2]+red[3]+red[4]+red[5]+red[6]+red[7];
        float inv = 1.f/s;
        Srow[tid] = e0*inv;
        Srow[tid+256] = e1*inv;
        __syncthreads();
    }
}

// ---------------- LayerNorm ----------------
__global__ __launch_bounds__(256) void ln_k(
    const float* __restrict__ sc, const float* __restrict__ bs, float* __restrict__ Y)
{
    int row = blockIdx.x;
    const float* x = g_x + (size_t)row*D_;
    float* y = Y + (size_t)row*D_;
    __shared__ float r1[8], r2[8];
    int tid = threadIdx.x;
    float v0=x[tid], v1=x[tid+256], v2=x[tid+512];
    float s = v0+v1+v2, q = v0*v0+v1*v1+v2*v2;
    #pragma unroll
    for (int o=16;o;o>>=1) {
        s += __shfl_xor_sync(~0u, s, o);
        q += __shfl_xor_sync(~0u, q, o);
    }
    if ((tid&31)==0) { r1[tid>>5]=s; r2[tid>>5]=q; }
    __syncthreads();
    s = r1[0]+r1[1]+r1[2]+r1[3]+r1[4]+r1[5]+r1[6]+r1[7];
    q = r2[0]+r2[1]+r2[2]+r2[3]+r2[4]+r2[5]+r2[6]+r2[7];
    float mu = s * (1.f/D_);
    float var = q * (1.f/D_) - mu*mu;
    float r = rsqrtf(var + 1e-5f);
    y[tid]     = (v0-mu)*r*sc[tid]     + bs[tid];
    y[tid+256] = (v1-mu)*r*sc[tid+256] + bs[tid+256];
    y[tid+512] = (v2-mu)*r*sc[tid+512] + bs[tid+512];
}

// ---------------- host ----------------
extern "C" void kernel_launch(void* const* d_in, const int* in_sizes, int n_in,
                              void* d_out, int out_size) {
    const float* q    = (const float*)d_in[0];
    const float* k    = (const float*)d_in[1];
    const float* v    = (const float*)d_in[2];
    const float* ploc = (const float*)d_in[3];
    const float* txt  = (const float*)d_in[4];
    const void*  mask = d_in[5];
    const float* Wq = (const float*)d_in[6],  *bq = (const float*)d_in[7];
    const float* Wk = (const float*)d_in[8],  *bk = (const float*)d_in[9];
    const float* Wv = (const float*)d_in[10], *bv = (const float*)d_in[11];
    const float* Wfc= (const float*)d_in[12], *bfc= (const float*)d_in[13];
    const float* Wc = (const float*)d_in[14], *bc = (const float*)d_in[15];
    const float* lns= (const float*)d_in[16], *lnb= (const float*)d_in[17];

    float* y = (float*)d_out;
    float* P = y + (size_t)B_*L_*D_;          // fused_attn region (B,H,L,L)

    void *qh_, *kh_, *vh_, *qt_, *ctx_, *x_, *sw_;
    cudaGetSymbolAddress(&qh_, g_qh);  cudaGetSymbolAddress(&kh_, g_kh);
    cudaGetSymbolAddress(&vh_, g_vh);  cudaGetSymbolAddress(&qt_, g_qt);
    cudaGetSymbolAddress(&ctx_, g_ctx); cudaGetSymbolAddress(&x_, g_x);
    cudaGetSymbolAddress(&sw_, g_sw);
    float* qh = (float*)qh_; float* kh = (float*)kh_; float* vh = (float*)vh_;
    float* qt = (float*)qt_; float* ctx = (float*)ctx_; float* xx = (float*)x_;
    float* sw = (float*)sw_;

    const int M = B_*L_;
    detect_mask_k<<<1,256>>>((const unsigned int*)mask);
    add_txt_k<<<(M*D_ + 255)/256, 256>>>(q, txt);

    // Q/K/V projections in ONE launch (z selects weight set)
    {
        GArgs g{};
        g.A0=q; g.A1=k; g.A2=v; g.B0=Wq; g.B1=Wk; g.B2=Wv;
        g.bi0=bq; g.bi1=bk; g.bi2=bv; g.C0=qh; g.C1=kh; g.C2=vh;
        g.resid=nullptr; g.M=M; g.N=D_; g.K=D_; g.lda=D_; g.ldb=D_; g.ldc=D_;
        g.nSets=3; g.Hp=1; g.alpha=1.f;
        gemm_k<false,4><<<dim3(M/128, D_/128, 3), 256>>>(g);
    }
    // cond: (B*L,768) @ (768,72)
    {
        GArgs g{};
        g.A0=qt; g.B0=Wc; g.bi0=bc; g.C0=sw;
        g.M=M; g.N=72; g.K=D_; g.lda=D_; g.ldb=72; g.ldc=72;
        g.nSets=1; g.Hp=1; g.alpha=1.f;
        gemm_k<false,2><<<dim3(M/128, 2, 1), 256>>>(g);
    }
    // S = scale * Q @ K^T per (b,h) -> P region of d_out
    {
        GArgs g{};
        g.A0=qh; g.B0=kh; g.C0=P;
        g.M=L_; g.N=L_; g.K=64; g.lda=D_; g.ldb=D_; g.ldc=L_;
        g.aSB=(long long)L_*D_; g.aSH=64;
        g.bSB=(long long)L_*D_; g.bSH=64;
        g.cSB=(long long)H_*L_*L_; g.cSH=(long long)L_*L_;
        g.nSets=1; g.Hp=H_; g.alpha=0.125f;
        gemm_k<true,4><<<dim3(L_/128, L_/128, B_*H_), 256>>>(g);
    }
    // fused spatial gate + masked softmax, in place on P
    fuse_softmax_k<<<M, 256>>>(ploc, mask, P);
    // ctx = P @ V per (b,h)
    {
        GArgs g{};
        g.A0=P; g.B0=vh; g.C0=ctx;
        g.M=L_; g.N=64; g.K=L_; g.lda=L_; g.ldb=D_; g.ldc=D_;
        g.aSB=(long long)H_*L_*L_; g.aSH=(long long)L_*L_;
        g.bSB=(long long)L_*D_; g.bSH=64;
        g.cSB=(long long)L_*D_; g.cSH=64;
        g.nSets=1; g.Hp=H_; g.alpha=1.f;
        gemm_k<false,2><<<dim3(L_/128, 1, B_*H_), 256>>>(g);
    }
    // x = ctx @ Wfc + bfc + q
    {
        GArgs g{};
        g.A0=ctx; g.B0=Wfc; g.bi0=bfc; g.resid=q; g.C0=xx;
        g.M=M; g.N=D_; g.K=D_; g.lda=D_; g.ldb=D_; g.ldc=D_;
        g.nSets=1; g.Hp=1; g.alpha=1.f;
        gemm_k<false,4><<<dim3(M/128, D_/128, 1), 256>>>(g);
    }
    // y = LayerNorm(x)
    ln_k<<<M, 256>>>(lns, lnb, y);
}